// round 1
// baseline (speedup 1.0000x reference)
#include <cuda_runtime.h>
#include <cuda_bf16.h>

// Geometry
#define NK    64
#define PLANE (256 * 64)        // i stride (elements)
#define CH    (256 * 256 * 64)  // channel / batch-plane stride (elements)

// Global accumulators (scratch via __device__ globals — no allocation)
__device__ double g_div_sum;
__device__ double g_smooth_sum;
__device__ float  g_sbin[2][63];   // sum dz per (b,k)
__device__ float  g_qbin[2][63];   // sum dz^2 per (b,k)

#define ARR4(v) { (v).x, (v).y, (v).z, (v).w }

__device__ __forceinline__ float blk_reduce_256(float v) {
    __shared__ float sh[8];
    #pragma unroll
    for (int o = 16; o > 0; o >>= 1) v += __shfl_down_sync(0xffffffffu, v, o);
    int w = threadIdx.x >> 5;
    if ((threadIdx.x & 31) == 0) sh[w] = v;
    __syncthreads();
    if (w == 0) {
        v = (threadIdx.x < 8) ? sh[threadIdx.x] : 0.f;
        #pragma unroll
        for (int o = 4; o > 0; o >>= 1) v += __shfl_down_sync(0xffffffffu, v, o);
    }
    return v;  // valid in thread 0
}

// ---------------------------------------------------------------------------
// Kernel A: loss_div. One thread = (b, i, j) column x 4 k-values (float4).
// 16 lanes cover k=0..63; warp = 2 columns. Per-k-plane quantities
// (pbx0, pbx1, qby0, qby1, sbz, P) are computed once and shared between the
// two cells that touch each plane; the k+4 boundary plane comes from the
// next lane via shfl (width 16).
// ---------------------------------------------------------------------------
__global__ void __launch_bounds__(256) kA_div(const float* __restrict__ outp,
                                              const float* __restrict__ tgt) {
    const int tid = threadIdx.x;
    const int k4  = tid & 15;
    const int col = tid >> 4;     // 0..15 columns per block
    const int kk  = 4 * k4;
    const unsigned FM = 0xffffffffu;
    float acc = 0.f;

    const int NT = 2 * 255 * 16;  // tiles (b, i, j-tile)
    for (int tile = blockIdx.x; tile < NT; tile += gridDim.x) {
        int jt = tile & 15;
        int bi = tile >> 4;
        int i  = bi % 255;
        int b  = bi / 255;
        int j  = jt * 16 + col;
        bool valid = (j < 255);
        int jc = valid ? j : 254;   // clamp so inactive lanes still load legally

        const float* zp  = outp + (size_t)b * CH + (size_t)i * PLANE + (size_t)jc * NK + kk;
        const float* xp  = tgt + (size_t)b * 3 * CH + (size_t)i * PLANE + (size_t)jc * NK + kk;
        const float* yp  = xp + CH;
        const float* wp  = yp + CH;

        float4 z00f = *(const float4*)zp;
        float4 z01f = *(const float4*)(zp + NK);
        float4 z10f = *(const float4*)(zp + PLANE);
        float4 z11f = *(const float4*)(zp + PLANE + NK);
        float4 x00f = *(const float4*)xp;
        float4 x01f = *(const float4*)(xp + NK);
        float4 x10f = *(const float4*)(xp + PLANE);
        float4 x11f = *(const float4*)(xp + PLANE + NK);
        float4 y00f = *(const float4*)yp;
        float4 y01f = *(const float4*)(yp + NK);
        float4 y10f = *(const float4*)(yp + PLANE);
        float4 y11f = *(const float4*)(yp + PLANE + NK);
        float4 w00f = *(const float4*)wp;
        float4 w01f = *(const float4*)(wp + NK);
        float4 w10f = *(const float4*)(wp + PLANE);
        float4 w11f = *(const float4*)(wp + PLANE + NK);

        float bx00[4] = ARR4(x00f), bx01[4] = ARR4(x01f), bx10[4] = ARR4(x10f), bx11[4] = ARR4(x11f);
        float by00[4] = ARR4(y00f), by01[4] = ARR4(y01f), by10[4] = ARR4(y10f), by11[4] = ARR4(y11f);
        float bz00[4] = ARR4(w00f), bz01[4] = ARR4(w01f), bz10[4] = ARR4(w10f), bz11[4] = ARR4(w11f);
        float zz00[4] = ARR4(z00f), zz01[4] = ARR4(z01f), zz10[4] = ARR4(z10f), zz11[4] = ARR4(z11f);

        float p0[5], p1[5], q0[5], q1[5], sz[5], P[5];
        float Z00[5], Z01[5], Z10[5], Z11[5];
        #pragma unroll
        for (int t = 0; t < 4; t++) {
            p0[t] = bx00[t] + bx01[t];                    // BX, di = 0 (both dj)
            p1[t] = bx10[t] + bx11[t];                    // BX, di = 1
            q0[t] = by00[t] + by10[t];                    // BY, dj = 0
            q1[t] = by01[t] + by11[t];                    // BY, dj = 1
            sz[t] = (bz00[t] + bz01[t]) + (bz10[t] + bz11[t]);
            P[t]  = ((bx00[t] + bx10[t] + bx11[t]) * (zz00[t] - zz10[t])
                   + (bx01[t] + bx11[t] + bx10[t]) * (zz01[t] - zz11[t])
                   + (by10[t] + by11[t] + by01[t]) * (zz10[t] - zz11[t])
                   + (by00[t] + by01[t] + by11[t]) * (zz00[t] - zz01[t])) * (1.f / 6.f);
            Z00[t] = zz00[t]; Z01[t] = zz01[t]; Z10[t] = zz10[t]; Z11[t] = zz11[t];
        }
        // boundary plane kk+4 from next lane (its t=0). Lane 15 gets garbage
        // (self-value), but its t=3 cell (k=63) is excluded by the guard.
        p0[4]  = __shfl_down_sync(FM, p0[0], 1, 16);
        p1[4]  = __shfl_down_sync(FM, p1[0], 1, 16);
        q0[4]  = __shfl_down_sync(FM, q0[0], 1, 16);
        q1[4]  = __shfl_down_sync(FM, q1[0], 1, 16);
        sz[4]  = __shfl_down_sync(FM, sz[0], 1, 16);
        P[4]   = __shfl_down_sync(FM, P[0], 1, 16);
        Z00[4] = __shfl_down_sync(FM, Z00[0], 1, 16);
        Z01[4] = __shfl_down_sync(FM, Z01[0], 1, 16);
        Z10[4] = __shfl_down_sync(FM, Z10[0], 1, 16);
        Z11[4] = __shfl_down_sync(FM, Z11[0], 1, 16);

        if (valid) {
            #pragma unroll
            for (int t = 0; t < 4; t++) {
                if (kk + t < 63) {
                    float d00 = fabsf(Z00[t + 1] - Z00[t]);
                    float d01 = fabsf(Z01[t + 1] - Z01[t]);
                    float d10 = fabsf(Z10[t + 1] - Z10[t]);
                    float d11 = fabsf(Z11[t + 1] - Z11[t]);
                    float A1 = (p1[t] + p1[t + 1]) * (d10 + d11);
                    float A2 = (p0[t] + p0[t + 1]) * (d00 + d01);
                    float A3 = (q1[t] + q1[t + 1]) * (d01 + d11);
                    float A4 = (q0[t] + q0[t + 1]) * (d00 + d10);
                    float num = 0.125f * ((A1 - A2) + (A3 - A4))
                              + 0.25f * (sz[t + 1] - sz[t])
                              + (P[t + 1] - P[t]);
                    float sx  = (p0[t] + p1[t]) + (p0[t + 1] + p1[t + 1]);
                    float sy  = (q0[t] + q1[t]) + (q0[t + 1] + q1[t + 1]);
                    float szz = sz[t] + sz[t + 1];
                    float den = 0.015625f * (sx * sx) + 0.015625f * (sy * sy)
                              + 0.015625f * (szz * szz) + 1e-10f;
                    acc += __fdividef(num * num, den);
                }
            }
        }
    }

    float tot = blk_reduce_256(acc);
    if (threadIdx.x == 0) atomicAdd(&g_div_sum, (double)tot);
}

// ---------------------------------------------------------------------------
// Kernel B: loss_smooth (7-point stencil on dz^2) + loss_std (per-(b,k) sum
// and sumsq of dz). Reads only z. Same lane-to-k mapping as kernel A.
// ---------------------------------------------------------------------------
__global__ void __launch_bounds__(256) kB_smooth_std(const float* __restrict__ outp) {
    const int tid = threadIdx.x;
    const int k4  = tid & 15;
    const int col = tid >> 4;
    const int kk  = 4 * k4;
    const unsigned FM = 0xffffffffu;

    __shared__ float shS[2][63];
    __shared__ float shQ[2][63];
    for (int t = tid; t < 126; t += 256) { ((float*)shS)[t] = 0.f; ((float*)shQ)[t] = 0.f; }
    __syncthreads();

    float accL = 0.f;
    float sS0[4] = {0.f, 0.f, 0.f, 0.f}, sQ0[4] = {0.f, 0.f, 0.f, 0.f};
    float sS1[4] = {0.f, 0.f, 0.f, 0.f}, sQ1[4] = {0.f, 0.f, 0.f, 0.f};

    const int NT = 2 * 256 * 16;
    for (int tile = blockIdx.x; tile < NT; tile += gridDim.x) {
        int jt = tile & 15;
        int bi = tile >> 4;
        int i  = bi & 255;
        int b  = bi >> 8;
        int j  = jt * 16 + col;       // always valid for std
        int im = (i > 0)   ? i - 1 : i;
        int ip = (i < 255) ? i + 1 : i;
        int jm = (j > 0)   ? j - 1 : j;
        int jp = (j < 255) ? j + 1 : j;

        const float* base = outp + (size_t)b * CH;
        float4 cf  = *(const float4*)(base + (size_t)i  * PLANE + (size_t)j  * NK + kk);
        float4 af  = *(const float4*)(base + (size_t)im * PLANE + (size_t)j  * NK + kk);
        float4 bf  = *(const float4*)(base + (size_t)ip * PLANE + (size_t)j  * NK + kk);
        float4 ef  = *(const float4*)(base + (size_t)i  * PLANE + (size_t)jm * NK + kk);
        float4 ff  = *(const float4*)(base + (size_t)i  * PLANE + (size_t)jp * NK + kk);

        float zc[5] = ARR4(cf); float za[5] = ARR4(af); float zb[5] = ARR4(bf);
        float ze[5] = ARR4(ef); float zf[5] = ARR4(ff);
        zc[4] = __shfl_down_sync(FM, cf.x, 1, 16);
        za[4] = __shfl_down_sync(FM, af.x, 1, 16);
        zb[4] = __shfl_down_sync(FM, bf.x, 1, 16);
        ze[4] = __shfl_down_sync(FM, ef.x, 1, 16);
        zf[4] = __shfl_down_sync(FM, ff.x, 1, 16);

        float m0 = (b == 0) ? 1.f : 0.f;
        float m1 = 1.f - m0;

        float d2c[4], d2a[4], d2b[4], d2e[4], d2f[4];
        #pragma unroll
        for (int t = 0; t < 4; t++) {
            float d = zc[t + 1] - zc[t];
            d2c[t] = d * d;
            if (kk + t < 63) {      // std accumulation (center column only)
                sS0[t] += m0 * d;  sQ0[t] += m0 * d * d;
                sS1[t] += m1 * d;  sQ1[t] += m1 * d * d;
            }
            float da = za[t + 1] - za[t]; d2a[t] = da * da;
            float db = zb[t + 1] - zb[t]; d2b[t] = db * db;
            float de = ze[t + 1] - ze[t]; d2e[t] = de * de;
            float df = zf[t + 1] - zf[t]; d2f[t] = df * df;
        }
        float d2p = __shfl_up_sync(FM, d2c[3], 1, 16);   // dz2 at kk-1
        float d2n = __shfl_down_sync(FM, d2c[0], 1, 16); // dz2 at kk+4

        if (i >= 1 && i <= 254 && j >= 1 && j <= 254) {
            #pragma unroll
            for (int t = 0; t < 4; t++) {
                int k = kk + t;
                if (k >= 1 && k <= 61) {
                    float km = (t > 0) ? d2c[t - 1] : d2p;
                    float kp = (t < 3) ? d2c[t + 1] : d2n;
                    float lap = 6.f * d2c[t] - d2a[t] - d2b[t] - d2e[t] - d2f[t] - km - kp;
                    accL += lap * lap;
                }
            }
        }
    }

    // std: thread partials -> shared bins -> global bins
    #pragma unroll
    for (int t = 0; t < 4; t++) {
        if (kk + t < 63) {
            atomicAdd(&shS[0][kk + t], sS0[t]);
            atomicAdd(&shQ[0][kk + t], sQ0[t]);
            atomicAdd(&shS[1][kk + t], sS1[t]);
            atomicAdd(&shQ[1][kk + t], sQ1[t]);
        }
    }
    __syncthreads();
    for (int t = tid; t < 126; t += 256) {
        atomicAdd(&((float*)g_sbin)[t], ((float*)shS)[t]);
        atomicAdd(&((float*)g_qbin)[t], ((float*)shQ)[t]);
    }

    float tot = blk_reduce_256(accL);
    if (threadIdx.x == 0) atomicAdd(&g_smooth_sum, (double)tot);
}

// ---------------------------------------------------------------------------
// Zero + finalize
// ---------------------------------------------------------------------------
__global__ void kZ_zero() {
    int t = threadIdx.x;
    if (t == 0) { g_div_sum = 0.0; g_smooth_sum = 0.0; }
    if (t < 126) { ((float*)g_sbin)[t] = 0.f; ((float*)g_qbin)[t] = 0.f; }
}

__global__ void kC_final(float* out) {
    int t = threadIdx.x;
    float v = 0.f;
    if (t < 126) {
        float S = ((float*)g_sbin)[t];
        float Q = ((float*)g_qbin)[t];
        float var = (Q - S * S * (1.0f / 65536.0f)) * (1.0f / 65535.0f);
        v = sqrtf(fmaxf(var, 0.f));
    }
    __shared__ float sh[4];
    #pragma unroll
    for (int o = 16; o > 0; o >>= 1) v += __shfl_down_sync(0xffffffffu, v, o);
    if ((t & 31) == 0) sh[t >> 5] = v;
    __syncthreads();
    if (t == 0) {
        float tot = sh[0] + sh[1] + sh[2] + sh[3];
        double lstd = (double)(tot / 126.f);
        out[0] = (float)(g_div_sum * (1.0e9 / 8193150.0));
        out[1] = (float)(g_smooth_sum * (10.0 / 7870952.0) + lstd * 100.0);
    }
}

extern "C" void kernel_launch(void* const* d_in, const int* in_sizes, int n_in,
                              void* d_out, int out_size) {
    const float* outp = (const float*)d_in[0];
    const float* tgt  = (const float*)d_in[1];
    if (n_in >= 2 && in_sizes[0] > in_sizes[1]) {  // defensive: outputs is the smaller tensor
        const float* tmp = outp; outp = tgt; tgt = tmp;
    }
    float* out = (float*)d_out;

    kZ_zero<<<1, 128>>>();
    kA_div<<<1184, 256>>>(outp, tgt);
    kB_smooth_std<<<1184, 256>>>(outp);
    kC_final<<<1, 128>>>(out);
}

// round 2
// speedup vs baseline: 1.0196x; 1.0196x over previous
#include <cuda_runtime.h>
#include <cuda_bf16.h>

#define NK    64
#define PLANE (256 * 64)
#define CH    (256 * 256 * 64)
#define NSEG  9
#define NBLK  (2 * 16 * NSEG)   // 288

__device__ double g_div_sum;
__device__ double g_smooth_sum;
__device__ float  g_sbin[2][63];
__device__ float  g_qbin[2][63];
__device__ unsigned g_done;

struct Row {
    float bxj[4], bxp[4], byj[4], byp[4], szr[4];
    float bxjS, bxpS, byjS, bypS, szrS;   // t=4 (shuffled from next lane's t=0)
    float zj[5], zp[5];
};

__device__ __forceinline__ void step(
    Row& P, Row& C, int gi, int i0, int i1, bool jdiv, bool jsm, int kk,
    const float* __restrict__ zb, const float* __restrict__ xb,
    const float* __restrict__ yb, const float* __restrict__ wb,
    size_t offj, size_t offm, size_t offp,
    float d2C2[4], float d2C1[4], float& d2p1, float& d2n1,
    float d2L1[4], float d2R1[4],
    float sS[4], float sQ[4], float& accD, float& accL)
{
    const unsigned FM = 0xffffffffu;
    int gic = gi < 0 ? 0 : (gi > 255 ? 255 : gi);
    size_t ro = (size_t)gic * PLANE;

    float4 zjm = *(const float4*)(zb + ro + offm);
    float4 zjf = *(const float4*)(zb + ro + offj);
    float4 zjp = *(const float4*)(zb + ro + offp);
    float4 xjf = *(const float4*)(xb + ro + offj);
    float4 xjp = *(const float4*)(xb + ro + offp);
    float4 yjf = *(const float4*)(yb + ro + offj);
    float4 yjp = *(const float4*)(yb + ro + offp);
    float4 wjf = *(const float4*)(wb + ro + offj);
    float4 wjp = *(const float4*)(wb + ro + offp);

    float zm[5];
    zm[0] = zjm.x; zm[1] = zjm.y; zm[2] = zjm.z; zm[3] = zjm.w;
    C.zj[0] = zjf.x; C.zj[1] = zjf.y; C.zj[2] = zjf.z; C.zj[3] = zjf.w;
    C.zp[0] = zjp.x; C.zp[1] = zjp.y; C.zp[2] = zjp.z; C.zp[3] = zjp.w;
    C.bxj[0] = xjf.x; C.bxj[1] = xjf.y; C.bxj[2] = xjf.z; C.bxj[3] = xjf.w;
    C.bxp[0] = xjp.x; C.bxp[1] = xjp.y; C.bxp[2] = xjp.z; C.bxp[3] = xjp.w;
    C.byj[0] = yjf.x; C.byj[1] = yjf.y; C.byj[2] = yjf.z; C.byj[3] = yjf.w;
    C.byp[0] = yjp.x; C.byp[1] = yjp.y; C.byp[2] = yjp.z; C.byp[3] = yjp.w;
    C.szr[0] = wjf.x + wjp.x; C.szr[1] = wjf.y + wjp.y;
    C.szr[2] = wjf.z + wjp.z; C.szr[3] = wjf.w + wjp.w;

    // k+4 boundary values via shuffle (width 16; lane 15 garbage is guarded off)
    zm[4]   = __shfl_down_sync(FM, zm[0],      1, 16);
    C.zj[4] = __shfl_down_sync(FM, C.zj[0],    1, 16);
    C.zp[4] = __shfl_down_sync(FM, C.zp[0],    1, 16);
    C.bxjS  = __shfl_down_sync(FM, C.bxj[0],   1, 16);
    C.bxpS  = __shfl_down_sync(FM, C.bxp[0],   1, 16);
    C.byjS  = __shfl_down_sync(FM, C.byj[0],   1, 16);
    C.bypS  = __shfl_down_sync(FM, C.byp[0],   1, 16);
    C.szrS  = __shfl_down_sync(FM, C.szr[0],   1, 16);

    // d2 for this row (3 columns)
    float d2C0[4], d2L0[4], d2R0[4];
    #pragma unroll
    for (int t = 0; t < 4; t++) {
        float dc = C.zj[t + 1] - C.zj[t]; d2C0[t] = dc * dc;
        float dl = zm[t + 1]   - zm[t];   d2L0[t] = dl * dl;
        float dr = C.zp[t + 1] - C.zp[t]; d2R0[t] = dr * dr;
    }
    float d2p0 = __shfl_up_sync(FM, d2C0[3], 1, 16);
    float d2n0 = __shfl_down_sync(FM, d2C0[0], 1, 16);

    // std accumulation for owned rows (center column)
    if (gi >= i0 && gi < i1) {
        #pragma unroll
        for (int t = 0; t < 4; t++) if (kk + t < 63) {
            float d = C.zj[t + 1] - C.zj[t];
            sS[t] += d; sQ[t] += d * d;
        }
    }

    // div cell between rows P (gi-1) and C (gi)
    if (gi - 1 >= i0 && gi - 1 < i1 && gi <= 255) {
        float p0l[5], p1l[5], q0l[5], q1l[5], szl[5], Pl[5];
        #pragma unroll
        for (int t = 0; t < 5; t++) {
            float pbxj = (t < 4) ? P.bxj[t] : P.bxjS;
            float pbxp = (t < 4) ? P.bxp[t] : P.bxpS;
            float pbyj = (t < 4) ? P.byj[t] : P.byjS;
            float pbyp = (t < 4) ? P.byp[t] : P.bypS;
            float psz  = (t < 4) ? P.szr[t] : P.szrS;
            float cbxj = (t < 4) ? C.bxj[t] : C.bxjS;
            float cbxp = (t < 4) ? C.bxp[t] : C.bxpS;
            float cbyj = (t < 4) ? C.byj[t] : C.byjS;
            float cbyp = (t < 4) ? C.byp[t] : C.bypS;
            float csz  = (t < 4) ? C.szr[t] : C.szrS;
            float pzj = P.zj[t], pzp = P.zp[t];
            float czj = C.zj[t], czp = C.zp[t];
            p0l[t] = pbxj + pbxp;
            p1l[t] = cbxj + cbxp;
            q0l[t] = pbyj + cbyj;
            q1l[t] = pbyp + cbyp;
            szl[t] = psz + csz;
            Pl[t] = ((pbxj + cbxj + cbxp) * (pzj - czj)
                   + (pbxp + cbxp + cbxj) * (pzp - czp)
                   + (cbyj + cbyp + pbyp) * (czj - czp)
                   + (pbyj + pbyp + cbyp) * (pzj - pzp)) * (1.f / 6.f);
        }
        if (jdiv) {
            #pragma unroll
            for (int t = 0; t < 4; t++) if (kk + t < 63) {
                float d00 = fabsf(P.zj[t + 1] - P.zj[t]);
                float d01 = fabsf(P.zp[t + 1] - P.zp[t]);
                float d10 = fabsf(C.zj[t + 1] - C.zj[t]);
                float d11 = fabsf(C.zp[t + 1] - C.zp[t]);
                float A1 = (p1l[t] + p1l[t + 1]) * (d10 + d11);
                float A2 = (p0l[t] + p0l[t + 1]) * (d00 + d01);
                float A3 = (q1l[t] + q1l[t + 1]) * (d01 + d11);
                float A4 = (q0l[t] + q0l[t + 1]) * (d00 + d10);
                float num = 0.125f * ((A1 - A2) + (A3 - A4))
                          + 0.25f * (szl[t + 1] - szl[t])
                          + (Pl[t + 1] - Pl[t]);
                float sx  = (p0l[t] + p1l[t]) + (p0l[t + 1] + p1l[t + 1]);
                float sy  = (q0l[t] + q1l[t]) + (q0l[t + 1] + q1l[t + 1]);
                float szz = szl[t] + szl[t + 1];
                float den = 0.015625f * (sx * sx + sy * sy + szz * szz) + 1e-10f;
                accD += __fdividef(num * num, den);
            }
        }
    }

    // smooth lap for center row gi-1
    int ic = gi - 1;
    if (ic >= i0 && ic < i1 && ic >= 1 && ic <= 254 && gi <= 255 && jsm) {
        #pragma unroll
        for (int t = 0; t < 4; t++) {
            int k = kk + t;
            if (k >= 1 && k <= 61) {
                float km = (t > 0) ? d2C1[t - 1] : d2p1;
                float kp = (t < 3) ? d2C1[t + 1] : d2n1;
                float lap = 6.f * d2C1[t] - d2C2[t] - d2C0[t]
                          - d2L1[t] - d2R1[t] - km - kp;
                accL += lap * lap;
            }
        }
    }

    // rotate d2 history
    #pragma unroll
    for (int t = 0; t < 4; t++) {
        d2C2[t] = d2C1[t]; d2C1[t] = d2C0[t];
        d2L1[t] = d2L0[t]; d2R1[t] = d2R0[t];
    }
    d2p1 = d2p0; d2n1 = d2n0;
}

__global__ void __launch_bounds__(256, 2) kFused(const float* __restrict__ zg,
                                                 const float* __restrict__ tg,
                                                 float* __restrict__ out) {
    const int tid = threadIdx.x;
    const int k4  = tid & 15;
    const int col = tid >> 4;
    const int kk  = 4 * k4;

    int bid  = blockIdx.x;
    int jt   = bid & 15;
    int rest = bid >> 4;
    int seg  = rest % NSEG;
    int b    = rest / NSEG;
    int i0   = (seg * 256) / NSEG;
    int i1   = ((seg + 1) * 256) / NSEG;

    int j   = jt * 16 + col;
    int jmc = (j > 0)   ? j - 1 : 0;
    int jpc = (j < 255) ? j + 1 : 255;
    bool jdiv = (j < 255);
    bool jsm  = (j >= 1 && j <= 254);

    const float* zb = zg + (size_t)b * CH + kk;
    const float* xb = tg + (size_t)b * 3 * CH + kk;
    const float* yb = xb + CH;
    const float* wb = yb + CH;
    size_t offj = (size_t)j * NK, offm = (size_t)jmc * NK, offp = (size_t)jpc * NK;

    __shared__ float shS[63], shQ[63];
    for (int t = tid; t < 63; t += 256) { shS[t] = 0.f; shQ[t] = 0.f; }
    __syncthreads();

    Row RA, RB;
    #pragma unroll
    for (int t = 0; t < 5; t++) { RA.zj[t] = 0.f; RA.zp[t] = 0.f; }
    #pragma unroll
    for (int t = 0; t < 4; t++) {
        RA.bxj[t] = RA.bxp[t] = RA.byj[t] = RA.byp[t] = RA.szr[t] = 0.f;
    }
    RA.bxjS = RA.bxpS = RA.byjS = RA.bypS = RA.szrS = 0.f;

    float d2C2[4] = {0,0,0,0}, d2C1[4] = {0,0,0,0};
    float d2L1[4] = {0,0,0,0}, d2R1[4] = {0,0,0,0};
    float d2p1 = 0.f, d2n1 = 0.f;
    float sS[4] = {0,0,0,0}, sQ[4] = {0,0,0,0};
    float accD = 0.f, accL = 0.f;

    int iters = (i1 - i0) + 2;
    int gi = i0 - 1;
    for (int it = 0; it < iters; it += 2) {
        step(RA, RB, gi, i0, i1, jdiv, jsm, kk, zb, xb, yb, wb,
             offj, offm, offp, d2C2, d2C1, d2p1, d2n1, d2L1, d2R1,
             sS, sQ, accD, accL);
        gi++;
        if (it + 1 < iters) {
            step(RB, RA, gi, i0, i1, jdiv, jsm, kk, zb, xb, yb, wb,
                 offj, offm, offp, d2C2, d2C1, d2p1, d2n1, d2L1, d2R1,
                 sS, sQ, accD, accL);
            gi++;
        }
    }

    // std bins: thread partials -> shared -> global
    #pragma unroll
    for (int t = 0; t < 4; t++) if (kk + t < 63) {
        atomicAdd(&shS[kk + t], sS[t]);
        atomicAdd(&shQ[kk + t], sQ[t]);
    }
    __syncthreads();
    for (int t = tid; t < 63; t += 256) {
        atomicAdd(&g_sbin[b][t], shS[t]);
        atomicAdd(&g_qbin[b][t], shQ[t]);
    }

    // block reduce accD, accL
    {
        __shared__ float sa[8], sb2[8];
        const unsigned FM = 0xffffffffu;
        #pragma unroll
        for (int o = 16; o > 0; o >>= 1) {
            accD += __shfl_down_sync(FM, accD, o);
            accL += __shfl_down_sync(FM, accL, o);
        }
        int w = tid >> 5;
        if ((tid & 31) == 0) { sa[w] = accD; sb2[w] = accL; }
        __syncthreads();
        if (tid == 0) {
            float tD = 0.f, tL = 0.f;
            #pragma unroll
            for (int q = 0; q < 8; q++) { tD += sa[q]; tL += sb2[q]; }
            atomicAdd(&g_div_sum, (double)tD);
            atomicAdd(&g_smooth_sum, (double)tL);
        }
    }

    // last-block finalize
    __threadfence();
    __shared__ bool islast;
    if (tid == 0) {
        unsigned v = atomicAdd(&g_done, 1u);
        islast = (v == gridDim.x - 1);
    }
    __syncthreads();
    if (islast) {
        if (tid == 0) g_done = 0;
        float v = 0.f;
        if (tid < 126) {
            float S = ((float*)g_sbin)[tid];
            float Q = ((float*)g_qbin)[tid];
            float var = (Q - S * S * (1.0f / 65536.0f)) * (1.0f / 65535.0f);
            v = sqrtf(fmaxf(var, 0.f));
        }
        __shared__ float sf[8];
        const unsigned FM = 0xffffffffu;
        #pragma unroll
        for (int o = 16; o > 0; o >>= 1) v += __shfl_down_sync(FM, v, o);
        if ((tid & 31) == 0) sf[tid >> 5] = v;
        __syncthreads();
        if (tid == 0) {
            float tot = 0.f;
            #pragma unroll
            for (int q = 0; q < 8; q++) tot += sf[q];
            double lstd = (double)(tot / 126.f);
            out[0] = (float)(g_div_sum * (1.0e9 / 8193150.0));
            out[1] = (float)(g_smooth_sum * (10.0 / 7870952.0) + lstd * 100.0);
        }
    }
}

__global__ void kZ_zero() {
    int t = threadIdx.x;
    if (t == 0) { g_div_sum = 0.0; g_smooth_sum = 0.0; g_done = 0u; }
    if (t < 126) { ((float*)g_sbin)[t] = 0.f; ((float*)g_qbin)[t] = 0.f; }
}

extern "C" void kernel_launch(void* const* d_in, const int* in_sizes, int n_in,
                              void* d_out, int out_size) {
    const float* outp = (const float*)d_in[0];
    const float* tgt  = (const float*)d_in[1];
    if (n_in >= 2 && in_sizes[0] > in_sizes[1]) {
        const float* tmp = outp; outp = tgt; tgt = tmp;
    }
    float* out = (float*)d_out;

    kZ_zero<<<1, 128>>>();
    kFused<<<NBLK, 256>>>(outp, tgt, out);
}